// round 3
// baseline (speedup 1.0000x reference)
#include <cuda_runtime.h>
#include <cuda_bf16.h>
#include <math.h>

// ---------------------------------------------------------------------------
// GraphSAGE fraud detector. R3: bf16 gather path + fused final colsum.
// ---------------------------------------------------------------------------

#define MAXN 100000
#define MAXE 1600000
#define F 64

__device__ int   g_deg[MAXN];
__device__ int   g_rowstart[MAXN];
__device__ int   g_cursor[MAXN];
__device__ int   g_srcs[MAXE];
__device__ float g_aggr[(size_t)MAXN * F];
__device__ float g_bufA[(size_t)MAXN * F];
__device__ float g_bufB[(size_t)MAXN * F];
__device__ __nv_bfloat16 g_xb[(size_t)MAXN * F];
__device__ __nv_bfloat16 g_bufAb[(size_t)MAXN * F];
__device__ __nv_bfloat16 g_bufBb[(size_t)MAXN * F];
__device__ float g_colsum[F];
__device__ int   g_bsum[256];
__device__ int   g_boff[256];

// ---------------------------------------------------------------------------
__global__ void init_kernel(int nNodes) {
    int i = blockIdx.x * blockDim.x + threadIdx.x;
    if (i < nNodes) g_deg[i] = 0;
    if (i < F) g_colsum[i] = 0.f;
}

__global__ void hist_kernel(const int* __restrict__ dst, int E) {
    int e = blockIdx.x * blockDim.x + threadIdx.x;
    if (e < E) atomicAdd(&g_deg[dst[e]], 1);
}

// --- 3-phase parallel exclusive scan over degrees (2 nodes / thread) -------
__global__ void scan_pass1(int nNodes) {
    int t = threadIdx.x, b = blockIdx.x;
    int base = (b * 256 + t) * 2;
    int s = 0;
    if (base < nNodes) s += g_deg[base];
    if (base + 1 < nNodes) s += g_deg[base + 1];
    __shared__ int sh[256];
    sh[t] = s;
    __syncthreads();
    for (int o = 128; o > 0; o >>= 1) {
        if (t < o) sh[t] += sh[t + o];
        __syncthreads();
    }
    if (t == 0) g_bsum[b] = sh[0];
}

__global__ void scan_pass2() {
    __shared__ int sh[256];
    int t = threadIdx.x;
    int v = g_bsum[t];
    sh[t] = v;
    __syncthreads();
    for (int o = 1; o < 256; o <<= 1) {
        int u = (t >= o) ? sh[t - o] : 0;
        __syncthreads();
        sh[t] += u;
        __syncthreads();
    }
    g_boff[t] = sh[t] - v;
}

__global__ void scan_pass3(int nNodes) {
    int t = threadIdx.x, b = blockIdx.x;
    int base = (b * 256 + t) * 2;
    int d0 = (base < nNodes) ? g_deg[base] : 0;
    int d1 = (base + 1 < nNodes) ? g_deg[base + 1] : 0;
    int s = d0 + d1;
    __shared__ int sh[256];
    sh[t] = s;
    __syncthreads();
    for (int o = 1; o < 256; o <<= 1) {
        int u = (t >= o) ? sh[t - o] : 0;
        __syncthreads();
        sh[t] += u;
        __syncthreads();
    }
    int pre = g_boff[b] + sh[t] - s;
    if (base < nNodes) { g_rowstart[base] = pre; g_cursor[base] = pre; }
    if (base + 1 < nNodes) { g_rowstart[base + 1] = pre + d0; g_cursor[base + 1] = pre + d0; }
}

__global__ void scatter_kernel(const int* __restrict__ src,
                               const int* __restrict__ dst, int E) {
    int e = blockIdx.x * blockDim.x + threadIdx.x;
    if (e < E) {
        int d = dst[e];
        int p = atomicAdd(&g_cursor[d], 1);
        g_srcs[p] = src[e];
    }
}

// --- x (fp32) -> bf16 shadow ----------------------------------------------
__global__ void tobf16_kernel(const float2* __restrict__ in,
                              __nv_bfloat162* __restrict__ out, int n2) {
    int i = blockIdx.x * blockDim.x + threadIdx.x;
    if (i < n2) {
        float2 v = in[i];
        out[i] = __floats2bfloat162_rn(v.x, v.y);
    }
}

// ---------------------------------------------------------------------------
// Mean aggregation from bf16 features, fp32 accumulate, fp32 output.
// One warp per destination node; lane handles 2 features (bf16x2 = 4B/lane,
// warp covers the 128B row).
__global__ void __launch_bounds__(256) aggregate_kernel(
    const __nv_bfloat162* __restrict__ hin, int nNodes) {
    int gw = (blockIdx.x * blockDim.x + threadIdx.x) >> 5;
    int lane = threadIdx.x & 31;
    if (gw >= nNodes) return;
    int start = g_rowstart[gw];
    int deg = g_deg[gw];
    float ax = 0.f, ay = 0.f;
    int i = 0;
    for (; i + 4 <= deg; i += 4) {
        int s0 = __ldg(&g_srcs[start + i + 0]);
        int s1 = __ldg(&g_srcs[start + i + 1]);
        int s2 = __ldg(&g_srcs[start + i + 2]);
        int s3 = __ldg(&g_srcs[start + i + 3]);
        float2 t0 = __bfloat1622float2(__ldg(hin + s0 * 32 + lane));
        float2 t1 = __bfloat1622float2(__ldg(hin + s1 * 32 + lane));
        float2 t2 = __bfloat1622float2(__ldg(hin + s2 * 32 + lane));
        float2 t3 = __bfloat1622float2(__ldg(hin + s3 * 32 + lane));
        ax += t0.x + t1.x + t2.x + t3.x;
        ay += t0.y + t1.y + t2.y + t3.y;
    }
    for (; i < deg; ++i) {
        int s = __ldg(&g_srcs[start + i]);
        float2 t = __bfloat1622float2(__ldg(hin + s * 32 + lane));
        ax += t.x;
        ay += t.y;
    }
    float inv = deg > 0 ? 1.0f / (float)deg : 0.f;
    ((float2*)(g_aggr + (size_t)gw * F))[lane] = make_float2(ax * inv, ay * inv);
}

// ---------------------------------------------------------------------------
// Fused dual GEMM with packed f32x2 FMA + BN + ReLU.
// Writes fp32 out (next layer's root term) and bf16 shadow (next gather).
#define WSTRIDE 68

__device__ __forceinline__ unsigned long long pack2(float v) {
    unsigned int u = __float_as_uint(v);
    unsigned long long r;
    asm("mov.b64 %0, {%1, %1};" : "=l"(r) : "r"(u));
    return r;
}

__device__ __forceinline__ void load_weights_T(
    const float* __restrict__ wl, const float* __restrict__ wr,
    float (*Wt)[WSTRIDE], int tid) {
    const float4* wl4 = (const float4*)wl;
    const float4* wr4 = (const float4*)wr;
    for (int i = tid; i < 1024; i += 256) {
        int j = i >> 4;
        int kc = (i & 15) << 2;
        float4 a = __ldg(wl4 + i);
        Wt[kc + 0][j] = a.x; Wt[kc + 1][j] = a.y;
        Wt[kc + 2][j] = a.z; Wt[kc + 3][j] = a.w;
        float4 b = __ldg(wr4 + i);
        Wt[64 + kc + 0][j] = b.x; Wt[64 + kc + 1][j] = b.y;
        Wt[64 + kc + 2][j] = b.z; Wt[64 + kc + 3][j] = b.w;
    }
}

__device__ __forceinline__ void dual_mm_row(
    const float* __restrict__ H, int row, const float (*Wt)[WSTRIDE],
    unsigned long long* acc2) {
    const float4* a4 = (const float4*)(g_aggr + (size_t)row * F);
    const float4* h4 = (const float4*)(H + (size_t)row * F);
#pragma unroll 1
    for (int kk = 0; kk < 8; ++kk) {
        const float4* sp = (kk < 4) ? a4 : h4;
        int base = (kk & 3) * 4;
        float4 v0 = __ldg(sp + base + 0);
        float4 v1 = __ldg(sp + base + 1);
        float4 v2 = __ldg(sp + base + 2);
        float4 v3 = __ldg(sp + base + 3);
        float a[16] = {v0.x, v0.y, v0.z, v0.w, v1.x, v1.y, v1.z, v1.w,
                       v2.x, v2.y, v2.z, v2.w, v3.x, v3.y, v3.z, v3.w};
        int kb = kk * 16;
#pragma unroll
        for (int k = 0; k < 16; ++k) {
            unsigned long long a2 = pack2(a[k]);
            const ulonglong2* wp = (const ulonglong2*)&Wt[kb + k][0];
#pragma unroll
            for (int j4 = 0; j4 < 16; ++j4) {
                ulonglong2 w = wp[j4];
                asm("fma.rn.f32x2 %0, %1, %2, %0;"
                    : "+l"(acc2[2 * j4 + 0]) : "l"(a2), "l"(w.x));
                asm("fma.rn.f32x2 %0, %1, %2, %0;"
                    : "+l"(acc2[2 * j4 + 1]) : "l"(a2), "l"(w.y));
            }
        }
    }
}

__global__ void __launch_bounds__(256, 2) gemm_bn_kernel(
    const float* __restrict__ H,
    const float* __restrict__ wl, const float* __restrict__ wr,
    const float* __restrict__ bl,
    const float* __restrict__ gn, const float* __restrict__ be,
    const float* __restrict__ mn, const float* __restrict__ vr,
    float* __restrict__ out, __nv_bfloat16* __restrict__ outb, int nNodes) {
    __shared__ __align__(16) float Wt[128][WSTRIDE];
    __shared__ float s_scale[F];
    __shared__ float s_shift[F];

    int tid = threadIdx.x;
    load_weights_T(wl, wr, Wt, tid);
    if (tid < F) {
        float sc = __ldg(&gn[tid]) * rsqrtf(__ldg(&vr[tid]) + 1e-5f);
        s_scale[tid] = sc;
        s_shift[tid] = (__ldg(&bl[tid]) - __ldg(&mn[tid])) * sc + __ldg(&be[tid]);
    }
    __syncthreads();

    int row = blockIdx.x * 256 + tid;
    if (row >= nNodes) return;

    unsigned long long acc2[32];
#pragma unroll
    for (int j2 = 0; j2 < 32; ++j2) acc2[j2] = 0ull;
    dual_mm_row(H, row, Wt, acc2);

    float o[F];
#pragma unroll
    for (int j2 = 0; j2 < 32; ++j2) {
        unsigned int lo, hi;
        asm("mov.b64 {%0, %1}, %2;" : "=r"(lo), "=r"(hi) : "l"(acc2[j2]));
        o[2 * j2 + 0] = fmaxf(fmaf(__uint_as_float(lo), s_scale[2 * j2 + 0],
                                   s_shift[2 * j2 + 0]), 0.f);
        o[2 * j2 + 1] = fmaxf(fmaf(__uint_as_float(hi), s_scale[2 * j2 + 1],
                                   s_shift[2 * j2 + 1]), 0.f);
    }
    float* orow = out + (size_t)row * F;
#pragma unroll
    for (int j = 0; j < F; j += 4)
        *(float4*)&orow[j] = make_float4(o[j], o[j + 1], o[j + 2], o[j + 3]);

    uint4* brow = (uint4*)(outb + (size_t)row * F);
#pragma unroll
    for (int c = 0; c < 8; ++c) {
        __nv_bfloat162 p0 = __floats2bfloat162_rn(o[8 * c + 0], o[8 * c + 1]);
        __nv_bfloat162 p1 = __floats2bfloat162_rn(o[8 * c + 2], o[8 * c + 3]);
        __nv_bfloat162 p2 = __floats2bfloat162_rn(o[8 * c + 4], o[8 * c + 5]);
        __nv_bfloat162 p3 = __floats2bfloat162_rn(o[8 * c + 6], o[8 * c + 7]);
        uint4 u;
        u.x = *(unsigned int*)&p0; u.y = *(unsigned int*)&p1;
        u.z = *(unsigned int*)&p2; u.w = *(unsigned int*)&p3;
        brow[c] = u;
    }
}

// Final layer: dual GEMM, no BN/ReLU, no row output — warp-reduce straight
// into the global column sums (bias deferred to head kernel).
__global__ void __launch_bounds__(256, 2) gemm_final_kernel(
    const float* __restrict__ H,
    const float* __restrict__ wl, const float* __restrict__ wr, int nNodes) {
    __shared__ __align__(16) float Wt[128][WSTRIDE];
    int tid = threadIdx.x;
    load_weights_T(wl, wr, Wt, tid);
    __syncthreads();

    int row = blockIdx.x * 256 + tid;
    bool valid = row < nNodes;

    unsigned long long acc2[32];
#pragma unroll
    for (int j2 = 0; j2 < 32; ++j2) acc2[j2] = 0ull;
    if (valid) dual_mm_row(H, row, Wt, acc2);

    int lane = tid & 31;
#pragma unroll
    for (int j2 = 0; j2 < 32; ++j2) {
        unsigned int lo, hi;
        asm("mov.b64 {%0, %1}, %2;" : "=r"(lo), "=r"(hi) : "l"(acc2[j2]));
        float v0 = __uint_as_float(lo);
        float v1 = __uint_as_float(hi);
#pragma unroll
        for (int o = 16; o > 0; o >>= 1) {
            v0 += __shfl_xor_sync(0xffffffffu, v0, o);
            v1 += __shfl_xor_sync(0xffffffffu, v1, o);
        }
        if (lane == 0) {
            atomicAdd(&g_colsum[2 * j2 + 0], v0);
            atomicAdd(&g_colsum[2 * j2 + 1], v1);
        }
    }
}

// head: mean -> +b_l2 -> Linear(64,64)+ReLU -> Linear(64,1) -> sigmoid
__global__ void head_kernel(const float* __restrict__ bl2,
                            const float* __restrict__ cw1,
                            const float* __restrict__ cb1,
                            const float* __restrict__ cw2,
                            const float* __restrict__ cb2,
                            float* __restrict__ outp, int nNodes) {
    __shared__ float mean[F];
    __shared__ float z[F];
    int t = threadIdx.x;
    mean[t] = g_colsum[t] / (float)nNodes + __ldg(&bl2[t]);
    __syncthreads();
    float s = __ldg(&cb1[t]);
#pragma unroll
    for (int j = 0; j < F; ++j) s = fmaf(mean[j], __ldg(&cw1[t * F + j]), s);
    z[t] = fmaxf(s, 0.f);
    __syncthreads();
    if (t == 0) {
        float o = __ldg(&cb2[0]);
#pragma unroll
        for (int i = 0; i < F; ++i) o = fmaf(z[i], __ldg(&cw2[i]), o);
        outp[0] = 1.f / (1.f + expf(-o));
    }
}

// ---------------------------------------------------------------------------
extern "C" void kernel_launch(void* const* d_in, const int* in_sizes, int n_in,
                              void* d_out, int out_size) {
    const float* x    = (const float*)d_in[0];
    const int*   eidx = (const int*)d_in[1];
    const float* w_l0 = (const float*)d_in[2];
    const float* b_l0 = (const float*)d_in[3];
    const float* w_r0 = (const float*)d_in[4];
    const float* w_l1 = (const float*)d_in[5];
    const float* b_l1 = (const float*)d_in[6];
    const float* w_r1 = (const float*)d_in[7];
    const float* w_l2 = (const float*)d_in[8];
    const float* b_l2 = (const float*)d_in[9];
    const float* w_r2 = (const float*)d_in[10];
    const float* g0   = (const float*)d_in[11];
    const float* be0  = (const float*)d_in[12];
    const float* m0   = (const float*)d_in[13];
    const float* v0   = (const float*)d_in[14];
    const float* g1   = (const float*)d_in[15];
    const float* be1  = (const float*)d_in[16];
    const float* m1   = (const float*)d_in[17];
    const float* v1   = (const float*)d_in[18];
    const float* cw1  = (const float*)d_in[19];
    const float* cb1  = (const float*)d_in[20];
    const float* cw2  = (const float*)d_in[21];
    const float* cb2  = (const float*)d_in[22];
    float* out = (float*)d_out;

    int nN = in_sizes[0] / F;
    int E = in_sizes[1] / 2;
    if (nN > MAXN) nN = MAXN;
    if (E > MAXE) E = MAXE;
    const int* srcp = eidx;
    const int* dstp = eidx + E;

    float *bufA, *bufB;
    __nv_bfloat16 *xb, *bufAb, *bufBb;
    cudaGetSymbolAddress((void**)&bufA, g_bufA);
    cudaGetSymbolAddress((void**)&bufB, g_bufB);
    cudaGetSymbolAddress((void**)&xb, g_xb);
    cudaGetSymbolAddress((void**)&bufAb, g_bufAb);
    cudaGetSymbolAddress((void**)&bufBb, g_bufBb);

    int tb = 256;
    init_kernel<<<(nN + tb - 1) / tb, tb>>>(nN);
    hist_kernel<<<(E + tb - 1) / tb, tb>>>(dstp, E);
    scan_pass1<<<256, 256>>>(nN);
    scan_pass2<<<1, 256>>>();
    scan_pass3<<<256, 256>>>(nN);
    scatter_kernel<<<(E + tb - 1) / tb, tb>>>(srcp, dstp, E);
    int n2 = nN * 32;
    tobf16_kernel<<<(n2 + tb - 1) / tb, tb>>>((const float2*)x,
                                              (__nv_bfloat162*)xb, n2);

    int aggBlocks = (nN + 7) / 8;
    int gemmBlocks = (nN + 255) / 256;

    // Layer 0: x -> bufA(+bufAb)
    aggregate_kernel<<<aggBlocks, tb>>>((const __nv_bfloat162*)xb, nN);
    gemm_bn_kernel<<<gemmBlocks, tb>>>(x, w_l0, w_r0, b_l0, g0, be0, m0, v0,
                                       bufA, bufAb, nN);
    // Layer 1: bufA -> bufB(+bufBb)
    aggregate_kernel<<<aggBlocks, tb>>>((const __nv_bfloat162*)bufAb, nN);
    gemm_bn_kernel<<<gemmBlocks, tb>>>(bufA, w_l1, w_r1, b_l1, g1, be1, m1, v1,
                                       bufB, bufBb, nN);
    // Layer 2: bufB -> column sums directly
    aggregate_kernel<<<aggBlocks, tb>>>((const __nv_bfloat162*)bufBb, nN);
    gemm_final_kernel<<<gemmBlocks, tb>>>(bufB, w_l2, w_r2, nN);

    head_kernel<<<1, F>>>(b_l2, cw1, cb1, cw2, cb2, out, nN);
}

// round 5
// speedup vs baseline: 1.0725x; 1.0725x over previous
#include <cuda_runtime.h>
#include <cuda_bf16.h>
#include <math.h>

// ---------------------------------------------------------------------------
// GraphSAGE fraud detector. R5 (= R4 resubmit after infra failure):
// bf16 inter-layer storage, spill-free chunked GEMM epilogue, fused final
// colsum reduction.
// ---------------------------------------------------------------------------

#define MAXN 100000
#define MAXE 1600000
#define F 64

__device__ int   g_deg[MAXN];
__device__ int   g_rowstart[MAXN];
__device__ int   g_cursor[MAXN];
__device__ int   g_srcs[MAXE];
__device__ float g_aggr[(size_t)MAXN * F];
__device__ __nv_bfloat16 g_xb[(size_t)MAXN * F];
__device__ __nv_bfloat16 g_bufAb[(size_t)MAXN * F];
__device__ __nv_bfloat16 g_bufBb[(size_t)MAXN * F];
__device__ float g_colsum[F];
__device__ int   g_bsum[256];
__device__ int   g_boff[256];

// ---------------------------------------------------------------------------
__global__ void init_kernel(int nNodes) {
    int i = blockIdx.x * blockDim.x + threadIdx.x;
    if (i < nNodes) g_deg[i] = 0;
    if (i < F) g_colsum[i] = 0.f;
}

__global__ void hist_kernel(const int* __restrict__ dst, int E) {
    int e = blockIdx.x * blockDim.x + threadIdx.x;
    if (e < E) atomicAdd(&g_deg[dst[e]], 1);
}

// --- 3-phase parallel exclusive scan over degrees (2 nodes / thread) -------
__global__ void scan_pass1(int nNodes) {
    int t = threadIdx.x, b = blockIdx.x;
    int base = (b * 256 + t) * 2;
    int s = 0;
    if (base < nNodes) s += g_deg[base];
    if (base + 1 < nNodes) s += g_deg[base + 1];
    __shared__ int sh[256];
    sh[t] = s;
    __syncthreads();
    for (int o = 128; o > 0; o >>= 1) {
        if (t < o) sh[t] += sh[t + o];
        __syncthreads();
    }
    if (t == 0) g_bsum[b] = sh[0];
}

__global__ void scan_pass2() {
    __shared__ int sh[256];
    int t = threadIdx.x;
    int v = g_bsum[t];
    sh[t] = v;
    __syncthreads();
    for (int o = 1; o < 256; o <<= 1) {
        int u = (t >= o) ? sh[t - o] : 0;
        __syncthreads();
        sh[t] += u;
        __syncthreads();
    }
    g_boff[t] = sh[t] - v;
}

__global__ void scan_pass3(int nNodes) {
    int t = threadIdx.x, b = blockIdx.x;
    int base = (b * 256 + t) * 2;
    int d0 = (base < nNodes) ? g_deg[base] : 0;
    int d1 = (base + 1 < nNodes) ? g_deg[base + 1] : 0;
    int s = d0 + d1;
    __shared__ int sh[256];
    sh[t] = s;
    __syncthreads();
    for (int o = 1; o < 256; o <<= 1) {
        int u = (t >= o) ? sh[t - o] : 0;
        __syncthreads();
        sh[t] += u;
        __syncthreads();
    }
    int pre = g_boff[b] + sh[t] - s;
    if (base < nNodes) { g_rowstart[base] = pre; g_cursor[base] = pre; }
    if (base + 1 < nNodes) { g_rowstart[base + 1] = pre + d0; g_cursor[base + 1] = pre + d0; }
}

__global__ void scatter_kernel(const int* __restrict__ src,
                               const int* __restrict__ dst, int E) {
    int e = blockIdx.x * blockDim.x + threadIdx.x;
    if (e < E) {
        int d = dst[e];
        int p = atomicAdd(&g_cursor[d], 1);
        g_srcs[p] = src[e];
    }
}

// --- x (fp32) -> bf16 shadow ----------------------------------------------
__global__ void tobf16_kernel(const float2* __restrict__ in,
                              __nv_bfloat162* __restrict__ out, int n2) {
    int i = blockIdx.x * blockDim.x + threadIdx.x;
    if (i < n2) {
        float2 v = in[i];
        out[i] = __floats2bfloat162_rn(v.x, v.y);
    }
}

// ---------------------------------------------------------------------------
// Mean aggregation from bf16 rows, fp32 accumulate, fp32 output.
// One warp per destination node; lane handles 2 features (bf16x2 / lane).
__global__ void __launch_bounds__(256) aggregate_kernel(
    const __nv_bfloat162* __restrict__ hin, int nNodes) {
    int gw = (blockIdx.x * blockDim.x + threadIdx.x) >> 5;
    int lane = threadIdx.x & 31;
    if (gw >= nNodes) return;
    int start = g_rowstart[gw];
    int deg = g_deg[gw];
    float ax = 0.f, ay = 0.f;
    int i = 0;
    for (; i + 4 <= deg; i += 4) {
        int s0 = __ldg(&g_srcs[start + i + 0]);
        int s1 = __ldg(&g_srcs[start + i + 1]);
        int s2 = __ldg(&g_srcs[start + i + 2]);
        int s3 = __ldg(&g_srcs[start + i + 3]);
        float2 t0 = __bfloat1622float2(__ldg(hin + s0 * 32 + lane));
        float2 t1 = __bfloat1622float2(__ldg(hin + s1 * 32 + lane));
        float2 t2 = __bfloat1622float2(__ldg(hin + s2 * 32 + lane));
        float2 t3 = __bfloat1622float2(__ldg(hin + s3 * 32 + lane));
        ax += t0.x + t1.x + t2.x + t3.x;
        ay += t0.y + t1.y + t2.y + t3.y;
    }
    for (; i < deg; ++i) {
        int s = __ldg(&g_srcs[start + i]);
        float2 t = __bfloat1622float2(__ldg(hin + s * 32 + lane));
        ax += t.x;
        ay += t.y;
    }
    float inv = deg > 0 ? 1.0f / (float)deg : 0.f;
    ((float2*)(g_aggr + (size_t)gw * F))[lane] = make_float2(ax * inv, ay * inv);
}

// ---------------------------------------------------------------------------
// Fused dual GEMM with packed f32x2 FMA.  Root term read from bf16 rows.
#define WSTRIDE 68

__device__ __forceinline__ unsigned long long pack2(float v) {
    unsigned int u = __float_as_uint(v);
    unsigned long long r;
    asm("mov.b64 %0, {%1, %1};" : "=l"(r) : "r"(u));
    return r;
}

__device__ __forceinline__ void load_weights_T(
    const float* __restrict__ wl, const float* __restrict__ wr,
    float (*Wt)[WSTRIDE], int tid) {
    const float4* wl4 = (const float4*)wl;
    const float4* wr4 = (const float4*)wr;
    for (int i = tid; i < 1024; i += 256) {
        int j = i >> 4;
        int kc = (i & 15) << 2;
        float4 a = __ldg(wl4 + i);
        Wt[kc + 0][j] = a.x; Wt[kc + 1][j] = a.y;
        Wt[kc + 2][j] = a.z; Wt[kc + 3][j] = a.w;
        float4 b = __ldg(wr4 + i);
        Wt[64 + kc + 0][j] = b.x; Wt[64 + kc + 1][j] = b.y;
        Wt[64 + kc + 2][j] = b.z; Wt[64 + kc + 3][j] = b.w;
    }
}

__device__ __forceinline__ void fma16(const float* a, int kb,
                                      const float (*Wt)[WSTRIDE],
                                      unsigned long long* acc2) {
#pragma unroll
    for (int k = 0; k < 16; ++k) {
        unsigned long long a2 = pack2(a[k]);
        const ulonglong2* wp = (const ulonglong2*)&Wt[kb + k][0];
#pragma unroll
        for (int j4 = 0; j4 < 16; ++j4) {
            ulonglong2 w = wp[j4];
            asm("fma.rn.f32x2 %0, %1, %2, %0;"
                : "+l"(acc2[2 * j4 + 0]) : "l"(a2), "l"(w.x));
            asm("fma.rn.f32x2 %0, %1, %2, %0;"
                : "+l"(acc2[2 * j4 + 1]) : "l"(a2), "l"(w.y));
        }
    }
}

// aggr term (fp32) for k<64, root term (bf16 row) for k>=64.
__device__ __forceinline__ void dual_mm_row(
    const __nv_bfloat16* __restrict__ Hb, int row,
    const float (*Wt)[WSTRIDE], unsigned long long* acc2) {
    const float4* a4 = (const float4*)(g_aggr + (size_t)row * F);
#pragma unroll 1
    for (int kk = 0; kk < 4; ++kk) {
        float4 v0 = __ldg(a4 + kk * 4 + 0);
        float4 v1 = __ldg(a4 + kk * 4 + 1);
        float4 v2 = __ldg(a4 + kk * 4 + 2);
        float4 v3 = __ldg(a4 + kk * 4 + 3);
        float a[16] = {v0.x, v0.y, v0.z, v0.w, v1.x, v1.y, v1.z, v1.w,
                       v2.x, v2.y, v2.z, v2.w, v3.x, v3.y, v3.z, v3.w};
        fma16(a, kk * 16, Wt, acc2);
    }
    const uint4* h4 = (const uint4*)(Hb + (size_t)row * F);  // 8 bf16 / uint4
#pragma unroll 1
    for (int kk = 0; kk < 4; ++kk) {
        uint4 u0 = __ldg(h4 + kk * 2 + 0);
        uint4 u1 = __ldg(h4 + kk * 2 + 1);
        float a[16];
        const unsigned int us[8] = {u0.x, u0.y, u0.z, u0.w, u1.x, u1.y, u1.z, u1.w};
#pragma unroll
        for (int q = 0; q < 8; ++q) {
            float2 f = __bfloat1622float2(*(const __nv_bfloat162*)&us[q]);
            a[2 * q] = f.x;
            a[2 * q + 1] = f.y;
        }
        fma16(a, 64 + kk * 16, Wt, acc2);
    }
}

__global__ void __launch_bounds__(256, 2) gemm_bn_kernel(
    const __nv_bfloat16* __restrict__ Hb,
    const float* __restrict__ wl, const float* __restrict__ wr,
    const float* __restrict__ bl,
    const float* __restrict__ gn, const float* __restrict__ be,
    const float* __restrict__ mn, const float* __restrict__ vr,
    __nv_bfloat16* __restrict__ outb, int nNodes) {
    __shared__ __align__(16) float Wt[128][WSTRIDE];
    __shared__ float s_scale[F];
    __shared__ float s_shift[F];

    int tid = threadIdx.x;
    load_weights_T(wl, wr, Wt, tid);
    if (tid < F) {
        float sc = __ldg(&gn[tid]) * rsqrtf(__ldg(&vr[tid]) + 1e-5f);
        s_scale[tid] = sc;
        s_shift[tid] = (__ldg(&bl[tid]) - __ldg(&mn[tid])) * sc + __ldg(&be[tid]);
    }
    __syncthreads();

    int row = blockIdx.x * 256 + tid;
    if (row >= nNodes) return;

    unsigned long long acc2[32];
#pragma unroll
    for (int j2 = 0; j2 < 32; ++j2) acc2[j2] = 0ull;
    dual_mm_row(Hb, row, Wt, acc2);

    // Chunked epilogue: 8 outputs at a time (keeps live regs ~acc2+8).
    uint4* brow = (uint4*)(outb + (size_t)row * F);
#pragma unroll
    for (int c = 0; c < 8; ++c) {
        float v[8];
#pragma unroll
        for (int q = 0; q < 4; ++q) {
            unsigned int lo, hi;
            asm("mov.b64 {%0, %1}, %2;" : "=r"(lo), "=r"(hi)
                : "l"(acc2[c * 4 + q]));
            int j = c * 8 + 2 * q;
            v[2 * q + 0] = fmaxf(fmaf(__uint_as_float(lo), s_scale[j + 0],
                                      s_shift[j + 0]), 0.f);
            v[2 * q + 1] = fmaxf(fmaf(__uint_as_float(hi), s_scale[j + 1],
                                      s_shift[j + 1]), 0.f);
        }
        __nv_bfloat162 p0 = __floats2bfloat162_rn(v[0], v[1]);
        __nv_bfloat162 p1 = __floats2bfloat162_rn(v[2], v[3]);
        __nv_bfloat162 p2 = __floats2bfloat162_rn(v[4], v[5]);
        __nv_bfloat162 p3 = __floats2bfloat162_rn(v[6], v[7]);
        uint4 u;
        u.x = *(unsigned int*)&p0; u.y = *(unsigned int*)&p1;
        u.z = *(unsigned int*)&p2; u.w = *(unsigned int*)&p3;
        brow[c] = u;
    }
}

// Final layer: dual GEMM, warp-reduce straight into global column sums.
__global__ void __launch_bounds__(256, 2) gemm_final_kernel(
    const __nv_bfloat16* __restrict__ Hb,
    const float* __restrict__ wl, const float* __restrict__ wr, int nNodes) {
    __shared__ __align__(16) float Wt[128][WSTRIDE];
    int tid = threadIdx.x;
    load_weights_T(wl, wr, Wt, tid);
    __syncthreads();

    int row = blockIdx.x * 256 + tid;
    bool valid = row < nNodes;

    unsigned long long acc2[32];
#pragma unroll
    for (int j2 = 0; j2 < 32; ++j2) acc2[j2] = 0ull;
    if (valid) dual_mm_row(Hb, row, Wt, acc2);

    int lane = tid & 31;
#pragma unroll
    for (int j2 = 0; j2 < 32; ++j2) {
        unsigned int lo, hi;
        asm("mov.b64 {%0, %1}, %2;" : "=r"(lo), "=r"(hi) : "l"(acc2[j2]));
        float v0 = __uint_as_float(lo);
        float v1 = __uint_as_float(hi);
#pragma unroll
        for (int o = 16; o > 0; o >>= 1) {
            v0 += __shfl_xor_sync(0xffffffffu, v0, o);
            v1 += __shfl_xor_sync(0xffffffffu, v1, o);
        }
        if (lane == 0) {
            atomicAdd(&g_colsum[2 * j2 + 0], v0);
            atomicAdd(&g_colsum[2 * j2 + 1], v1);
        }
    }
}

// head: mean -> +b_l2 -> Linear(64,64)+ReLU -> Linear(64,1) -> sigmoid
__global__ void head_kernel(const float* __restrict__ bl2,
                            const float* __restrict__ cw1,
                            const float* __restrict__ cb1,
                            const float* __restrict__ cw2,
                            const float* __restrict__ cb2,
                            float* __restrict__ outp, int nNodes) {
    __shared__ float mean[F];
    __shared__ float z[F];
    int t = threadIdx.x;
    mean[t] = g_colsum[t] / (float)nNodes + __ldg(&bl2[t]);
    __syncthreads();
    float s = __ldg(&cb1[t]);
#pragma unroll
    for (int j = 0; j < F; ++j) s = fmaf(mean[j], __ldg(&cw1[t * F + j]), s);
    z[t] = fmaxf(s, 0.f);
    __syncthreads();
    if (t == 0) {
        float o = __ldg(&cb2[0]);
#pragma unroll
        for (int i = 0; i < F; ++i) o = fmaf(z[i], __ldg(&cw2[i]), o);
        outp[0] = 1.f / (1.f + expf(-o));
    }
}

// ---------------------------------------------------------------------------
extern "C" void kernel_launch(void* const* d_in, const int* in_sizes, int n_in,
                              void* d_out, int out_size) {
    const float* x    = (const float*)d_in[0];
    const int*   eidx = (const int*)d_in[1];
    const float* w_l0 = (const float*)d_in[2];
    const float* b_l0 = (const float*)d_in[3];
    const float* w_r0 = (const float*)d_in[4];
    const float* w_l1 = (const float*)d_in[5];
    const float* b_l1 = (const float*)d_in[6];
    const float* w_r1 = (const float*)d_in[7];
    const float* w_l2 = (const float*)d_in[8];
    const float* b_l2 = (const float*)d_in[9];
    const float* w_r2 = (const float*)d_in[10];
    const float* g0   = (const float*)d_in[11];
    const float* be0  = (const float*)d_in[12];
    const float* m0   = (const float*)d_in[13];
    const float* v0   = (const float*)d_in[14];
    const float* g1   = (const float*)d_in[15];
    const float* be1  = (const float*)d_in[16];
    const float* m1   = (const float*)d_in[17];
    const float* v1   = (const float*)d_in[18];
    const float* cw1  = (const float*)d_in[19];
    const float* cb1  = (const float*)d_in[20];
    const float* cw2  = (const float*)d_in[21];
    const float* cb2  = (const float*)d_in[22];
    float* out = (float*)d_out;

    int nN = in_sizes[0] / F;
    int E = in_sizes[1] / 2;
    if (nN > MAXN) nN = MAXN;
    if (E > MAXE) E = MAXE;
    const int* srcp = eidx;
    const int* dstp = eidx + E;

    __nv_bfloat16 *xb, *bufAb, *bufBb;
    cudaGetSymbolAddress((void**)&xb, g_xb);
    cudaGetSymbolAddress((void**)&bufAb, g_bufAb);
    cudaGetSymbolAddress((void**)&bufBb, g_bufBb);

    int tb = 256;
    init_kernel<<<(nN + tb - 1) / tb, tb>>>(nN);
    hist_kernel<<<(E + tb - 1) / tb, tb>>>(dstp, E);
    scan_pass1<<<256, 256>>>(nN);
    scan_pass2<<<1, 256>>>();
    scan_pass3<<<256, 256>>>(nN);
    scatter_kernel<<<(E + tb - 1) / tb, tb>>>(srcp, dstp, E);
    int n2 = nN * 32;
    tobf16_kernel<<<(n2 + tb - 1) / tb, tb>>>((const float2*)x,
                                              (__nv_bfloat162*)xb, n2);

    int aggBlocks = (nN + 7) / 8;
    int gemmBlocks = (nN + 255) / 256;

    // Layer 0: xb -> bufAb
    aggregate_kernel<<<aggBlocks, tb>>>((const __nv_bfloat162*)xb, nN);
    gemm_bn_kernel<<<gemmBlocks, tb>>>(xb, w_l0, w_r0, b_l0, g0, be0, m0, v0,
                                       bufAb, nN);
    // Layer 1: bufAb -> bufBb
    aggregate_kernel<<<aggBlocks, tb>>>((const __nv_bfloat162*)bufAb, nN);
    gemm_bn_kernel<<<gemmBlocks, tb>>>(bufAb, w_l1, w_r1, b_l1, g1, be1, m1,
                                       v1, bufBb, nN);
    // Layer 2: bufBb -> column sums directly
    aggregate_kernel<<<aggBlocks, tb>>>((const __nv_bfloat162*)bufBb, nN);
    gemm_final_kernel<<<gemmBlocks, tb>>>(bufBb, w_l2, w_r2, nN);

    head_kernel<<<1, F>>>(b_l2, cw1, cb1, cw2, cb2, out, nN);
}